// round 14
// baseline (speedup 1.0000x reference)
#include <cuda_runtime.h>
#include <cuda_fp16.h>
#include <cstdint>

// SNNAutoencoder: B=65536, D=512, H=64, L=16, T=8
// Inputs: x[65536,512], W1[64,512], b1[64], W2[16,64], b2[16],
//         W3[64,16], b3[64], W4[512,64], b4[512]    Output: float32 [65536,512]

#define B_TOTAL 65536

// Scratch (static device arrays)
__device__ float              g_hin[(size_t)B_TOTAL * 64];      // 16 MB
__device__ unsigned long long g_masks[(size_t)B_TOTAL * 8];     //  4 MB packed s3
__device__ unsigned           g_w4f[512 * 32];                  // fp16x2 (0.5*W4) [c][kpair]
__device__ uint4              g_w1h[32 * 8 * 32];               // fp16 hi/lo B-frags [ks][j][lane]
__device__ uint4              g_w2f[8 * 32];                    // 0.5*W2 hi/lo B-frags [(nc*4+ks)][lane]
__device__ uint4              g_w3f[8 * 32];                    // 0.5*W3 hi/lo B-frags [nc][lane]

// ---------------------------------------------------------------------------
// helpers
// ---------------------------------------------------------------------------
__device__ __forceinline__ unsigned tanh2(unsigned h) {
    unsigned r;
    asm("tanh.approx.f16x2 %0, %1;" : "=r"(r) : "r"(h));
    return r;
}
__device__ __forceinline__ uint32_t smem_u32(const void* p) {
    uint32_t a;
    asm("{ .reg .u64 t; cvta.to.shared.u64 t, %1; cvt.u32.u64 %0, t; }" : "=r"(a) : "l"(p));
    return a;
}
__device__ __forceinline__ void cpa16(uint32_t dst, const void* src) {
    asm volatile("cp.async.ca.shared.global [%0], [%1], 16;" :: "r"(dst), "l"(src));
}
#define CPA_COMMIT() asm volatile("cp.async.commit_group;" ::: "memory")
#define CPA_WAIT0()  asm volatile("cp.async.wait_group 0;" ::: "memory")

// fp16 mma, f32 accum, accumulate into D
__device__ __forceinline__ void mma16816h(float* d, const unsigned* a,
                                          unsigned b0, unsigned b1) {
    asm volatile(
        "mma.sync.aligned.m16n8k16.row.col.f32.f16.f16.f32 "
        "{%0,%1,%2,%3}, {%4,%5,%6,%7}, {%8,%9}, {%0,%1,%2,%3};"
        : "+f"(d[0]), "+f"(d[1]), "+f"(d[2]), "+f"(d[3])
        : "r"(a[0]), "r"(a[1]), "r"(a[2]), "r"(a[3]), "r"(b0), "r"(b1));
}
// fp16 mma, f32 accum, explicit C (bias init)
__device__ __forceinline__ void mma16816h_c(float* d, const unsigned* a,
                                            unsigned b0, unsigned b1,
                                            float c0, float c1, float c2, float c3) {
    asm volatile(
        "mma.sync.aligned.m16n8k16.row.col.f32.f16.f16.f32 "
        "{%0,%1,%2,%3}, {%4,%5,%6,%7}, {%8,%9}, {%10,%11,%12,%13};"
        : "=f"(d[0]), "=f"(d[1]), "=f"(d[2]), "=f"(d[3])
        : "r"(a[0]), "r"(a[1]), "r"(a[2]), "r"(a[3]), "r"(b0), "r"(b1),
          "f"(c0), "f"(c1), "f"(c2), "f"(c3));
}
// fp16 mma, f16 accum (k3)
__device__ __forceinline__ void mma16816hh(unsigned* d, const unsigned* a,
                                           unsigned b0, unsigned b1) {
    asm volatile(
        "mma.sync.aligned.m16n8k16.row.col.f16.f16.f16.f16 "
        "{%0,%1}, {%2,%3,%4,%5}, {%6,%7}, {%0,%1};"
        : "+r"(d[0]), "+r"(d[1])
        : "r"(a[0]), "r"(a[1]), "r"(a[2]), "r"(a[3]), "r"(b0), "r"(b1));
}

// split float2 -> fp16x2 hi + lo (exact residual)
__device__ __forceinline__ unsigned split_hl(float2 f, unsigned& lo) {
    __half2 h = __floats2half2_rn(f.x, f.y);
    float2 hf = __half22float2(h);
    __half2 l = __floats2half2_rn(f.x - hf.x, f.y - hf.y);
    lo = *(unsigned*)&l;
    return *(unsigned*)&h;
}

// ---------------------------------------------------------------------------
// Kernel 0: pack 0.5*W4 (fp16x2), W1 (fp16 hi/lo B-frags),
//           0.5*W2 and 0.5*W3 (fp16 hi/lo B-frags for k2's MMAs)
// ---------------------------------------------------------------------------
__global__ void k0_pack(const float* __restrict__ W4,
                        const float* __restrict__ W1,
                        const float* __restrict__ W2,
                        const float* __restrict__ W3) {
    const int bid = blockIdx.x;
    const int tid = threadIdx.x;
    if (bid < 64) {
        const int idx = bid * 256 + tid;
        float w0 = 0.5f * W4[2 * idx], w1 = 0.5f * W4[2 * idx + 1];
        __half h0 = __float2half_rn(w0);
        __half h1 = __float2half_rn(w1);
        g_w4f[idx] = (unsigned)__half_as_ushort(h0) |
                     ((unsigned)__half_as_ushort(h1) << 16);
    } else if (bid < 96) {
        const int idx = (bid - 64) * 256 + tid;
        int ks = idx >> 8, j = (idx >> 5) & 7, lane = idx & 31;
        int g = lane >> 2, q = lane & 3;
        int n = 8 * j + g;
        const float* src = W1 + n * 512 + ks * 16;
        float2 f0 = make_float2(src[2 * q], src[2 * q + 1]);
        float2 f1 = make_float2(src[8 + 2 * q], src[8 + 2 * q + 1]);
        unsigned lo0, lo1;
        unsigned hi0 = split_hl(f0, lo0);
        unsigned hi1 = split_hl(f1, lo1);
        g_w1h[idx] = make_uint4(hi0, hi1, lo0, lo1);
    } else if (bid == 96) {
        int lane = tid & 31, set = tid >> 5;
        int nc = set >> 2, ks = set & 3;
        int g = lane >> 2, q = lane & 3;
        int i = 8 * nc + g;
        int k = 16 * ks + 2 * q;
        float2 f0 = make_float2(0.5f * W2[i * 64 + k], 0.5f * W2[i * 64 + k + 1]);
        float2 f1 = make_float2(0.5f * W2[i * 64 + k + 8], 0.5f * W2[i * 64 + k + 9]);
        unsigned lo0, lo1;
        unsigned hi0 = split_hl(f0, lo0);
        unsigned hi1 = split_hl(f1, lo1);
        g_w2f[set * 32 + lane] = make_uint4(hi0, hi1, lo0, lo1);
    } else {
        int lane = tid & 31, nc = tid >> 5;
        int g = lane >> 2, q = lane & 3;
        int j = 8 * nc + g;
        float2 f0 = make_float2(0.5f * W3[j * 16 + 2 * q], 0.5f * W3[j * 16 + 2 * q + 1]);
        float2 f1 = make_float2(0.5f * W3[j * 16 + 2 * q + 8], 0.5f * W3[j * 16 + 2 * q + 9]);
        unsigned lo0, lo1;
        unsigned hi0 = split_hl(f0, lo0);
        unsigned hi1 = split_hl(f1, lo1);
        g_w3f[nc * 32 + lane] = make_uint4(hi0, hi1, lo0, lo1);
    }
}

// ---------------------------------------------------------------------------
// Kernel 1: h_in = x @ W1^T + b1 via 3x fp16 mma.sync (hi/lo split). unchanged
// ---------------------------------------------------------------------------
__global__ void __launch_bounds__(256) k1_hin(const float* __restrict__ x,
                                              const float* __restrict__ b1) {
    extern __shared__ float smemf[];
    float* xs = smemf;                         // [128][68]  34816 B
    uint4* wf = (uint4*)(smemf + 8704);        // [1024]     16384 B

    const int tid = threadIdx.x;
    const int warp = tid >> 5, lane = tid & 31;
    const int g = lane >> 2, q = lane & 3;
    const int blockRow = blockIdx.x * 128;

    const uint32_t xs_a = smem_u32(xs);
    const uint32_t wf_a = smem_u32(wf);

    float d[8][4];
#pragma unroll
    for (int j = 0; j < 8; j++)
#pragma unroll
        for (int i = 0; i < 4; i++) d[j][i] = 0.0f;

    const int r0 = warp * 16 + g;
    const int r1 = r0 + 8;

    for (int ch = 0; ch < 8; ch++) {
        __syncthreads();
        const float* xsrc = x + (size_t)blockRow * 512 + ch * 64;
#pragma unroll
        for (int it = 0; it < 8; it++) {
            int fidx = it * 256 + tid;
            int rr = fidx >> 4, c4 = (fidx & 15) * 4;
            cpa16(xs_a + (rr * 68 + c4) * 4, xsrc + (size_t)rr * 512 + c4);
        }
        const uint4* sp = g_w1h + ch * 1024;
#pragma unroll
        for (int i = 0; i < 4; i++)
            cpa16(wf_a + (i * 256 + tid) * 16, sp + i * 256 + tid);
        CPA_COMMIT();
        CPA_WAIT0();
        __syncthreads();

#pragma unroll
        for (int ks = 0; ks < 4; ks++) {
            const int lc = ks * 16 + 2 * q;
            float2 f00 = *(const float2*)&xs[r0 * 68 + lc];
            float2 f10 = *(const float2*)&xs[r1 * 68 + lc];
            float2 f08 = *(const float2*)&xs[r0 * 68 + lc + 8];
            float2 f18 = *(const float2*)&xs[r1 * 68 + lc + 8];
            unsigned ahi[4], alo[4];
            ahi[0] = split_hl(f00, alo[0]);
            ahi[1] = split_hl(f10, alo[1]);
            ahi[2] = split_hl(f08, alo[2]);
            ahi[3] = split_hl(f18, alo[3]);

            const int base = ks * 256 + lane;
#pragma unroll
            for (int j = 0; j < 8; j++) {
                uint4 w = wf[base + j * 32];
                mma16816h(d[j], ahi, w.x, w.y);   // hi * hi
                mma16816h(d[j], ahi, w.z, w.w);   // hi * lo
                mma16816h(d[j], alo, w.x, w.y);   // lo * hi
            }
        }
    }

    float* o0 = &g_hin[(size_t)(blockRow + r0) * 64];
    float* o1 = &g_hin[(size_t)(blockRow + r1) * 64];
#pragma unroll
    for (int j = 0; j < 8; j++) {
        const float2 bb = *(const float2*)&b1[8 * j + 2 * q];
        float2 v0 = make_float2(d[j][0] + bb.x, d[j][1] + bb.y);
        float2 v1 = make_float2(d[j][2] + bb.x, d[j][3] + bb.y);
        *(float2*)&o0[8 * j + 2 * q] = v0;
        *(float2*)&o1[8 * j + 2 * q] = v1;
    }
}

// ---------------------------------------------------------------------------
// Kernel 2: LIF recurrence via tensor-core MMAs. Warp = 16 rows. (unchanged)
// ---------------------------------------------------------------------------
#define LIF1(VV, HH, BIT, FR) { float nv_ = fmaf(VV, 0.5f, HH); \
    bool s_ = nv_ >= 1.0f; (VV) = s_ ? 0.0f : nv_; if (s_) (FR) |= (BIT); }

__global__ void __launch_bounds__(128) k2_recur(const float* __restrict__ b2,
                                                const float* __restrict__ b3) {
    __shared__ float hs[64][68];
    __shared__ uint4 w2s[8][32];
    __shared__ uint4 w3s[8][32];

    const int tid = threadIdx.x;
    const int warp = tid >> 5, lane = tid & 31;
    const int g = lane >> 2, q = lane & 3;
    const int row0 = blockIdx.x * 64;

    for (int i = tid; i < 1024; i += 128) {
        int r = i >> 4, c4 = (i & 15) * 4;
        float4 v = *(const float4*)&g_hin[(size_t)(row0 + r) * 64 + c4];
        v.x *= 0.5f; v.y *= 0.5f; v.z *= 0.5f; v.w *= 0.5f;
        *(float4*)&hs[r][c4] = v;
    }
    for (int i = tid; i < 256; i += 128) {
        ((uint4*)w2s)[i] = g_w2f[i];
        ((uint4*)w3s)[i] = g_w3f[i];
    }
    __syncthreads();

    const int rA = warp * 16 + g;
    const int rB = rA + 8;

    float b2c[2][2], b3c[8][2];
#pragma unroll
    for (int nc = 0; nc < 2; nc++) {
        b2c[nc][0] = 0.5f * b2[8 * nc + 2 * q];
        b2c[nc][1] = 0.5f * b2[8 * nc + 2 * q + 1];
    }
#pragma unroll
    for (int nc = 0; nc < 8; nc++) {
        b3c[nc][0] = 0.5f * b3[8 * nc + 2 * q];
        b3c[nc][1] = 0.5f * b3[8 * nc + 2 * q + 1];
    }
    const unsigned be = 1u << (2 * q);
    const unsigned bo = be << 1;

    float v1[4][8];
    float v2[2][4];
    float v3[8][4];
#pragma unroll
    for (int ks = 0; ks < 4; ks++)
#pragma unroll
        for (int i = 0; i < 8; i++) v1[ks][i] = 0.0f;
#pragma unroll
    for (int nc = 0; nc < 2; nc++)
#pragma unroll
        for (int i = 0; i < 4; i++) v2[nc][i] = 0.0f;
#pragma unroll
    for (int nc = 0; nc < 8; nc++)
#pragma unroll
        for (int i = 0; i < 4; i++) v3[nc][i] = 0.0f;

    for (int t = 0; t < 8; t++) {
        float d2[2][4];
#pragma unroll
        for (int ks = 0; ks < 4; ks++) {
            const int c0 = 16 * ks + 2 * q;
            float2 hA0 = *(const float2*)&hs[rA][c0];
            float2 hB0 = *(const float2*)&hs[rB][c0];
            float2 hA1 = *(const float2*)&hs[rA][c0 + 8];
            float2 hB1 = *(const float2*)&hs[rB][c0 + 8];

            unsigned aw[4] = {0u, 0u, 0u, 0u};
            LIF1(v1[ks][0], hA0.x, 0x00003C00u, aw[0]);
            LIF1(v1[ks][1], hA0.y, 0x3C000000u, aw[0]);
            LIF1(v1[ks][2], hB0.x, 0x00003C00u, aw[1]);
            LIF1(v1[ks][3], hB0.y, 0x3C000000u, aw[1]);
            LIF1(v1[ks][4], hA1.x, 0x00003C00u, aw[2]);
            LIF1(v1[ks][5], hA1.y, 0x3C000000u, aw[2]);
            LIF1(v1[ks][6], hB1.x, 0x00003C00u, aw[3]);
            LIF1(v1[ks][7], hB1.y, 0x3C000000u, aw[3]);

#pragma unroll
            for (int nc = 0; nc < 2; nc++) {
                uint4 w = w2s[nc * 4 + ks][lane];
                if (ks == 0)
                    mma16816h_c(d2[nc], aw, w.x, w.y,
                                b2c[nc][0], b2c[nc][1], b2c[nc][0], b2c[nc][1]);
                else
                    mma16816h(d2[nc], aw, w.x, w.y);
                mma16816h(d2[nc], aw, w.z, w.w);
            }
        }

        unsigned s2f[4];
#pragma unroll
        for (int nc = 0; nc < 2; nc++) {
            unsigned frA = 0u, frB = 0u;
            LIF1(v2[nc][0], d2[nc][0], 0x00003C00u, frA);
            LIF1(v2[nc][1], d2[nc][1], 0x3C000000u, frA);
            LIF1(v2[nc][2], d2[nc][2], 0x00003C00u, frB);
            LIF1(v2[nc][3], d2[nc][3], 0x3C000000u, frB);
            s2f[nc * 2]     = frA;
            s2f[nc * 2 + 1] = frB;
        }

        unsigned mA0 = 0u, mA1 = 0u, mB0 = 0u, mB1 = 0u;
#pragma unroll
        for (int nc = 0; nc < 8; nc++) {
            uint4 w = w3s[nc][lane];
            float d3[4];
            mma16816h_c(d3, s2f, w.x, w.y,
                        b3c[nc][0], b3c[nc][1], b3c[nc][0], b3c[nc][1]);
            mma16816h(d3, s2f, w.z, w.w);

            const unsigned bitE = be << (8 * (nc & 3));
            const unsigned bitO = bo << (8 * (nc & 3));
            {
                float nv = fmaf(v3[nc][0], 0.5f, d3[0]);
                bool s = nv >= 1.0f; v3[nc][0] = s ? 0.0f : nv;
                if (s) { if (nc < 4) mA0 |= bitE; else mA1 |= bitE; }
            }
            {
                float nv = fmaf(v3[nc][1], 0.5f, d3[1]);
                bool s = nv >= 1.0f; v3[nc][1] = s ? 0.0f : nv;
                if (s) { if (nc < 4) mA0 |= bitO; else mA1 |= bitO; }
            }
            {
                float nv = fmaf(v3[nc][2], 0.5f, d3[2]);
                bool s = nv >= 1.0f; v3[nc][2] = s ? 0.0f : nv;
                if (s) { if (nc < 4) mB0 |= bitE; else mB1 |= bitE; }
            }
            {
                float nv = fmaf(v3[nc][3], 0.5f, d3[3]);
                bool s = nv >= 1.0f; v3[nc][3] = s ? 0.0f : nv;
                if (s) { if (nc < 4) mB0 |= bitO; else mB1 |= bitO; }
            }
        }

        mA0 |= __shfl_xor_sync(0xffffffffu, mA0, 1);
        mA1 |= __shfl_xor_sync(0xffffffffu, mA1, 1);
        mB0 |= __shfl_xor_sync(0xffffffffu, mB0, 1);
        mB1 |= __shfl_xor_sync(0xffffffffu, mB1, 1);
        mA0 |= __shfl_xor_sync(0xffffffffu, mA0, 2);
        mA1 |= __shfl_xor_sync(0xffffffffu, mA1, 2);
        mB0 |= __shfl_xor_sync(0xffffffffu, mB0, 2);
        mB1 |= __shfl_xor_sync(0xffffffffu, mB1, 2);

        if (q == 0) {
            g_masks[(size_t)(row0 + rA) * 8 + t] =
                (unsigned long long)mA0 | ((unsigned long long)mA1 << 32);
            g_masks[(size_t)(row0 + rB) * 8 + t] =
                (unsigned long long)mB0 | ((unsigned long long)mB1 << 32);
        }
    }
}

// ---------------------------------------------------------------------------
// Kernel 3: fp16 HMMA (f16 accum), warp covers 32 columns; accumulator
// chains SPLIT (4 independent 2-deep chains per (t,cc)) to expose MMA ILP.
// ---------------------------------------------------------------------------
__global__ void __launch_bounds__(256) k3_mma(const float* __restrict__ b4,
                                              float* __restrict__ out) {
    __shared__ uint4 sf0[8][4][32];   // [t][cc][lane] frag ks0/ks1, 16 KB
    __shared__ uint4 sf1[8][4][32];   // [t][cc][lane] frag ks2/ks3, 16 KB

    const int tid = threadIdx.x;
    const int warp = tid >> 5, lane = tid & 31;
    const int g = lane >> 2;
    const int q = lane & 3;
    const int colbase = blockIdx.y * 256 + warp * 32;
    const int c0 = colbase + g;
    const int c2 = colbase + 16 + g;

    unsigned af0[4][4], af1[4][4];
#pragma unroll
    for (int ks = 0; ks < 4; ks++) {
        af0[ks][0] = g_w4f[c0 * 32 + ks * 8 + q];
        af0[ks][1] = g_w4f[(c0 + 8) * 32 + ks * 8 + q];
        af0[ks][2] = g_w4f[c0 * 32 + ks * 8 + 4 + q];
        af0[ks][3] = g_w4f[(c0 + 8) * 32 + ks * 8 + 4 + q];
        af1[ks][0] = g_w4f[c2 * 32 + ks * 8 + q];
        af1[ks][1] = g_w4f[(c2 + 8) * 32 + ks * 8 + q];
        af1[ks][2] = g_w4f[c2 * 32 + ks * 8 + 4 + q];
        af1[ks][3] = g_w4f[(c2 + 8) * 32 + ks * 8 + 4 + q];
    }
    __half2 h0 = __float2half2_rn(0.5f * b4[c0]);
    __half2 h1 = __float2half2_rn(0.5f * b4[c0 + 8]);
    __half2 h2 = __float2half2_rn(0.5f * b4[c2]);
    __half2 h3 = __float2half2_rn(0.5f * b4[c2 + 8]);
    const unsigned ce0 = *(unsigned*)&h0, ce1 = *(unsigned*)&h1;
    const unsigned ce2 = *(unsigned*)&h2, ce3 = *(unsigned*)&h3;

    for (int it = 0; it < 4; it++) {
        const int bbase = blockIdx.x * 128 + it * 32;

        // Producer: warp w builds frags for t = w.
#pragma unroll
        for (int cc = 0; cc < 4; cc++) {
            const unsigned long long m = g_masks[(size_t)(bbase + cc * 8 + g) * 8 + warp];
            unsigned wv[4][2];
#pragma unroll
            for (int ks = 0; ks < 4; ks++) {
                unsigned xx = (unsigned)(m >> (ks * 16 + 2 * q));
                unsigned s0 = (unsigned)((int)(xx << 31) >> 31) & 0x00003C00u;
                unsigned s1 = (unsigned)((int)(xx << 30) >> 31) & 0x3C000000u;
                wv[ks][0] = s0 | s1;
                unsigned yy = (unsigned)(m >> (ks * 16 + 8 + 2 * q));
                unsigned s2 = (unsigned)((int)(yy << 31) >> 31) & 0x00003C00u;
                unsigned s3 = (unsigned)((int)(yy << 30) >> 31) & 0x3C000000u;
                wv[ks][1] = s2 | s3;
            }
            sf0[warp][cc][lane] = make_uint4(wv[0][0], wv[0][1], wv[1][0], wv[1][1]);
            sf1[warp][cc][lane] = make_uint4(wv[2][0], wv[2][1], wv[3][0], wv[3][1]);
        }
        __syncthreads();

        // Consumer: 4 independent 2-deep MMA chains per (t,cc).
#pragma unroll
        for (int cc = 0; cc < 4; cc++) {
            __half2 s00 = __float2half2_rn(0.0f);
            __half2 s01 = __float2half2_rn(0.0f);
            __half2 s10 = __float2half2_rn(0.0f);
            __half2 s11 = __float2half2_rn(0.0f);
#pragma unroll
            for (int t = 0; t < 8; t++) {
                uint4 fa = sf0[t][cc][lane];
                uint4 fb = sf1[t][cc][lane];

                unsigned d0a[2] = {ce0, ce1};
                unsigned d0b[2] = {0u, 0u};
                unsigned d1a[2] = {ce2, ce3};
                unsigned d1b[2] = {0u, 0u};
                mma16816hh(d0a, af0[0], fa.x, fa.y);
                mma16816hh(d0b, af0[1], fa.z, fa.w);
                mma16816hh(d1a, af1[0], fa.x, fa.y);
                mma16816hh(d1b, af1[1], fa.z, fa.w);
                mma16816hh(d0a, af0[2], fb.x, fb.y);
                mma16816hh(d0b, af0[3], fb.z, fb.w);
                mma16816hh(d1a, af1[2], fb.x, fb.y);
                mma16816hh(d1b, af1[3], fb.z, fb.w);

                __half2 m00 = __hadd2(*(__half2*)&d0a[0], *(__half2*)&d0b[0]);
                __half2 m01 = __hadd2(*(__half2*)&d0a[1], *(__half2*)&d0b[1]);
                __half2 m10 = __hadd2(*(__half2*)&d1a[0], *(__half2*)&d1b[0]);
                __half2 m11 = __hadd2(*(__half2*)&d1a[1], *(__half2*)&d1b[1]);

                unsigned t00 = tanh2(*(unsigned*)&m00);
                unsigned t01 = tanh2(*(unsigned*)&m01);
                unsigned t10 = tanh2(*(unsigned*)&m10);
                unsigned t11 = tanh2(*(unsigned*)&m11);
                s00 = __hadd2(s00, *(__half2*)&t00);
                s01 = __hadd2(s01, *(__half2*)&t01);
                s10 = __hadd2(s10, *(__half2*)&t10);
                s11 = __hadd2(s11, *(__half2*)&t11);
            }
            float2 f00 = __half22float2(s00);
            float2 f01 = __half22float2(s01);
            float2 f10 = __half22float2(s10);
            float2 f11 = __half22float2(s11);
            const int b0 = bbase + cc * 8 + 2 * q;
            float* ob0 = out + (size_t)b0 * 512;
            float* ob1 = out + (size_t)(b0 + 1) * 512;
            ob0[c0]      = fmaf(f00.x, 0.0625f, 0.5f);
            ob1[c0]      = fmaf(f00.y, 0.0625f, 0.5f);
            ob0[c0 + 8]  = fmaf(f01.x, 0.0625f, 0.5f);
            ob1[c0 + 8]  = fmaf(f01.y, 0.0625f, 0.5f);
            ob0[c2]      = fmaf(f10.x, 0.0625f, 0.5f);
            ob1[c2]      = fmaf(f10.y, 0.0625f, 0.5f);
            ob0[c2 + 8]  = fmaf(f11.x, 0.0625f, 0.5f);
            ob1[c2 + 8]  = fmaf(f11.y, 0.0625f, 0.5f);
        }
        __syncthreads();
    }
}

// ---------------------------------------------------------------------------
extern "C" void kernel_launch(void* const* d_in, const int* in_sizes, int n_in,
                              void* d_out, int out_size) {
    const float* x  = (const float*)d_in[0];
    const float* W1 = (const float*)d_in[1];
    const float* b1 = (const float*)d_in[2];
    const float* W2 = (const float*)d_in[3];
    const float* b2 = (const float*)d_in[4];
    const float* W3 = (const float*)d_in[5];
    const float* b3 = (const float*)d_in[6];
    const float* W4 = (const float*)d_in[7];
    const float* b4 = (const float*)d_in[8];
    float* out = (float*)d_out;

    static bool attr_set = false;
    if (!attr_set) {
        cudaFuncSetAttribute(k1_hin, cudaFuncAttributeMaxDynamicSharedMemorySize, 51200);
        attr_set = true;
    }

    k0_pack<<<98, 256>>>(W4, W1, W2, W3);
    k1_hin<<<B_TOTAL / 128, 256, 51200>>>(x, b1);
    k2_recur<<<B_TOTAL / 64, 128>>>(b2, b3);
    k3_mma<<<dim3(B_TOTAL / 128, 2), 256>>>(b4, out);
}